// round 13
// baseline (speedup 1.0000x reference)
#include <cuda_runtime.h>
#include <cstdint>

// ShapeConv via int8 mma.sync m16n8k32 (4096 MACs/instr, half the instruction
// count of bf16 k16) used ONLY to select argmax t per (b,o); a small second
// kernel recomputes the selected feature exactly in fp32. Legacy mma retires
// ~1 instr/4cyc/SM regardless of shape (measured R3-R12), so halving the
// instruction count is the only lever left.

#define BB 32
#define CC 3
#define LL 8192
#define OO 128
#define KW 64
#define WW (LL - KW + 1)   /* 8129 valid windows */
#define KRED 192
#define NBLK 296
#define NWRP (NBLK * 8)
#define WT_TOTAL (BB * 4 * 128)   /* 16384 warp-tiles: 32o x 64t */

#define AP8 208            /* A int8 row pitch bytes (192 data + 16: bank-free) */
#define APW8 52            /* pitch in words */
#define A_OFF 0u           /* 128*208 = 26624 B */
#define Q_OFF 26624u       /* 8 warps * 3c * 32 words = 3072 B */
#define P_OFF 29696u       /* 8 warps * 128 f32 = 4096 B */
#define SMEM_BYTES 33792

#define QSCALE 24.0f
#define INVS (1.0f / (QSCALE * QSCALE))
typedef unsigned long long ull;

__device__ ull g_max2[BB * OO];    // (mono(val)<<32 | t), zero-init, reset by finalize

__device__ __forceinline__ unsigned int f2mono(float f) {
    unsigned int u = __float_as_uint(f);
    return (u & 0x80000000u) ? ~u : (u | 0x80000000u);
}
// quantize 4 floats -> packed s8 word (bytes in increasing position order)
__device__ __forceinline__ uint32_t q4(float a, float b, float c, float d) {
    int q0 = __float2int_rn(fminf(fmaxf(a * QSCALE, -127.f), 127.f));
    int q1 = __float2int_rn(fminf(fmaxf(b * QSCALE, -127.f), 127.f));
    int q2 = __float2int_rn(fminf(fmaxf(c * QSCALE, -127.f), 127.f));
    int q3 = __float2int_rn(fminf(fmaxf(d * QSCALE, -127.f), 127.f));
    uint32_t b01 = __byte_perm((uint32_t)q0, (uint32_t)q1, 0x0040);
    uint32_t b23 = __byte_perm((uint32_t)q2, (uint32_t)q3, 0x0040);
    return __byte_perm(b01, b23, 0x5410);
}
__device__ __forceinline__ void mma_s8(int* d, uint32_t a0, uint32_t a1,
                                       uint32_t a2, uint32_t a3,
                                       uint32_t b0, uint32_t b1) {
    asm volatile(
        "mma.sync.aligned.m16n8k32.row.col.s32.s8.s8.s32 "
        "{%0,%1,%2,%3}, {%4,%5,%6,%7}, {%8,%9}, {%0,%1,%2,%3};"
        : "+r"(d[0]), "+r"(d[1]), "+r"(d[2]), "+r"(d[3])
        : "r"(a0), "r"(a1), "r"(a2), "r"(a3), "r"(b0), "r"(b1));
}

// ---------------- one warp-tile: 32 o x 64 t, K=192, int8 ----------------
template <bool EDGE>
__device__ __forceinline__ void process_tile(
    const float* __restrict__ xb, int t0, const uint32_t* __restrict__ A8,
    uint32_t* __restrict__ Qw, float* __restrict__ Pw,
    int b, int os, int lane, int g, int tg)
{
    __syncwarp();   // previous tile's Qw/Pw reads complete

    // ---- load 128-float x window per channel: prefix sums + int8 quant ----
    {
        int gi = t0 + 4 * lane;
        float4 c0, c1, c2;
        if (EDGE) {
            int i0 = min(gi, LL - 1), i1 = min(gi + 1, LL - 1),
                i2 = min(gi + 2, LL - 1), i3 = min(gi + 3, LL - 1);
            c0 = make_float4(xb[i0], xb[i1], xb[i2], xb[i3]);
            c1 = make_float4(xb[LL + i0], xb[LL + i1], xb[LL + i2], xb[LL + i3]);
            c2 = make_float4(xb[2*LL + i0], xb[2*LL + i1], xb[2*LL + i2], xb[2*LL + i3]);
        } else {
            c0 = *(const float4*)(xb + gi);
            c1 = *(const float4*)(xb + LL + gi);
            c2 = *(const float4*)(xb + 2 * LL + gi);
        }
        Qw[lane]      = q4(c0.x, c0.y, c0.z, c0.w);
        Qw[32 + lane] = q4(c1.x, c1.y, c1.z, c1.w);
        Qw[64 + lane] = q4(c2.x, c2.y, c2.z, c2.w);
        float s0 = c0.x*c0.x + c1.x*c1.x + c2.x*c2.x;
        float s1 = c0.y*c0.y + c1.y*c1.y + c2.y*c2.y;
        float s2 = c0.z*c0.z + c1.z*c1.z + c2.z*c2.z;
        float s3 = c0.w*c0.w + c1.w*c1.w + c2.w*c2.w;
        float e1 = s0, e2 = s0 + s1, e3 = e2 + s2, tot = e3 + s3;
        float sc = tot;
        #pragma unroll
        for (int d = 1; d < 32; d <<= 1) {
            float t = __shfl_up_sync(0xffffffffu, sc, d);
            if (lane >= d) sc += t;
        }
        float base = sc - tot;
        *(float4*)(Pw + 4*lane) = make_float4(base, base+e1, base+e2, base+e3);
    }
    __syncwarp();

    // ---- int8 MMA mainloop ----
    int acc[2][8][4];
    #pragma unroll
    for (int mi = 0; mi < 2; ++mi)
        #pragma unroll
        for (int nf = 0; nf < 8; ++nf)
            #pragma unroll
            for (int r = 0; r < 4; ++r) acc[mi][nf][r] = 0;

    const int lb   = g + 4 * tg;                 // B byte offset class
    const int bw   = lb >> 2;
    const uint32_t psel = 0x3210u + 0x1111u * (uint32_t)(lb & 3);
    const int arow = (os * 32 + g) * APW8 + tg;  // A word base (bytes: row*208+4tg)

    #pragma unroll
    for (int c = 0; c < CC; ++c) {
        const uint32_t* Qc = Qw + c * 32;
        uint32_t bbv[14];
        #pragma unroll
        for (int u = 0; u < 14; ++u)
            bbv[u] = __byte_perm(Qc[bw + 2*u], Qc[bw + 2*u + 1], psel);

        #pragma unroll
        for (int j = 0; j < 2; ++j) {
            const int kw = (c * 2 + j) * 8;      // k-step offset in words (32B)
            #pragma unroll
            for (int mi = 0; mi < 2; ++mi) {
                const int base = arow + mi * 16 * APW8 + kw;
                uint32_t a0 = A8[base];
                uint32_t a1 = A8[base + 8 * APW8];
                uint32_t a2 = A8[base + 4];
                uint32_t a3 = A8[base + 8 * APW8 + 4];
                #pragma unroll
                for (int nf = 0; nf < 8; ++nf)
                    mma_s8(acc[mi][nf], a0, a1, a2, a3,
                           bbv[nf + 4*j], bbv[nf + 4*j + 2]);
            }
        }
    }

    // ---- epilogue: (val, t) argmax per row, exact-win subtraction ----
    float mv[2][2];  int mx[2][2];
    #pragma unroll
    for (int mi = 0; mi < 2; ++mi)
        #pragma unroll
        for (int h = 0; h < 2; ++h) { mv[mi][h] = __int_as_float(0xff800000); mx[mi][h] = t0; }

    #pragma unroll
    for (int nf = 0; nf < 8; ++nf) {
        const int n0 = nf * 8 + 2 * tg;
        float w0 = 0.5f * (Pw[n0 + 64] - Pw[n0]);
        float w1 = 0.5f * (Pw[n0 + 65] - Pw[n0 + 1]);
        if (EDGE) {
            if (t0 + n0 >= WW)     w0 = __int_as_float(0x7f800000);
            if (t0 + n0 + 1 >= WW) w1 = __int_as_float(0x7f800000);
        }
        const int ti0 = t0 + n0, ti1 = t0 + n0 + 1;
        #pragma unroll
        for (int mi = 0; mi < 2; ++mi) {
            const int* d = acc[mi][nf];
            float f0 = fmaf(__int2float_rn(d[0]), INVS, -w0);
            float f1 = fmaf(__int2float_rn(d[1]), INVS, -w1);
            float f2 = fmaf(__int2float_rn(d[2]), INVS, -w0);
            float f3 = fmaf(__int2float_rn(d[3]), INVS, -w1);
            if (f0 > mv[mi][0]) { mv[mi][0] = f0; mx[mi][0] = ti0; }
            if (f1 > mv[mi][0]) { mv[mi][0] = f1; mx[mi][0] = ti1; }
            if (f2 > mv[mi][1]) { mv[mi][1] = f2; mx[mi][1] = ti0; }
            if (f3 > mv[mi][1]) { mv[mi][1] = f3; mx[mi][1] = ti1; }
        }
    }
    // reduce across the 4 tg-lanes sharing each row
    #pragma unroll
    for (int mi = 0; mi < 2; ++mi)
        #pragma unroll
        for (int h = 0; h < 2; ++h) {
            #pragma unroll
            for (int d = 1; d <= 2; d <<= 1) {
                float ov = __shfl_xor_sync(0xffffffffu, mv[mi][h], d);
                int   oi = __shfl_xor_sync(0xffffffffu, mx[mi][h], d);
                if (ov > mv[mi][h]) { mv[mi][h] = ov; mx[mi][h] = oi; }
            }
        }
    if (tg == 0) {
        #pragma unroll
        for (int mi = 0; mi < 2; ++mi)
            #pragma unroll
            for (int h = 0; h < 2; ++h) {
                int row = os * 32 + mi * 16 + h * 8 + g;
                ull pk = ((ull)f2mono(mv[mi][h]) << 32) | (unsigned)mx[mi][h];
                atomicMax(&g_max2[b * OO + row], pk);
            }
    }
}

extern "C" __global__ void __launch_bounds__(256, 2)
shapeconv_sel(const float* __restrict__ xg, const float* __restrict__ wg) {
    extern __shared__ char smem[];
    uint32_t* A8 = (uint32_t*)(smem + A_OFF);    // [128][52w] int8

    const int tid  = threadIdx.x;
    const int wid  = tid >> 5;
    const int lane = tid & 31;
    const int g    = lane >> 2;
    const int tg   = lane & 3;

    uint32_t* Qw = (uint32_t*)(smem + Q_OFF) + wid * 96;
    float*    Pw = (float*)(smem + P_OFF) + wid * 128;

    // ---- A staging: quantize weights to int8, coalesced float4 loads ----
    for (int i = tid; i < 128 * 48; i += 256) {
        int row = i / 48, wd = i % 48;
        float4 v = *(const float4*)(wg + row * KRED + 4 * wd);
        A8[row * APW8 + wd] = q4(v.x, v.y, v.z, v.w);
    }
    __syncthreads();

    // ---- warp-autonomous tiles: widx -> (os, tw, b); os fastest for x reuse
    const int gw = blockIdx.x * 8 + wid;
    for (int widx = gw; widx < WT_TOTAL; widx += NWRP) {
        const int os = widx & 3;
        const int tw = (widx >> 2) & 127;
        const int b  = widx >> 9;
        const int t0 = tw << 6;
        const float* xb = xg + b * CC * LL;
        if (tw == 127)
            process_tile<true >(xb, t0, A8, Qw, Pw, b, os, lane, g, tg);
        else
            process_tile<false>(xb, t0, A8, Qw, Pw, b, os, lane, g, tg);
    }
}

// ---- exact fp32 recompute of the selected feature per (b,o) + reset ----
extern "C" __global__ void __launch_bounds__(256)
shapeconv_exact(const float* __restrict__ xg, const float* __restrict__ wg,
                float* __restrict__ out) {
    const int wid  = threadIdx.x >> 5;
    const int lane = threadIdx.x & 31;
    const int gw   = blockIdx.x * 8 + wid;
    for (int u = gw; u < BB * OO; u += 128 * 8) {
        ull pk = g_max2[u];
        int t = (int)(unsigned)(pk & 0xffffffffu);
        int b = u >> 7, o = u & (OO - 1);
        float conv = 0.f, wsq = 0.f, xsq = 0.f;
        #pragma unroll
        for (int j = 0; j < 6; ++j) {
            int kl = lane + 32 * j;
            int c = kl >> 6, k = kl & 63;
            float wv = wg[o * KRED + kl];
            float xv = xg[(b * CC + c) * LL + t + k];
            conv = fmaf(wv, xv, conv);
            wsq  = fmaf(wv, wv, wsq);
            xsq  = fmaf(xv, xv, xsq);
        }
        #pragma unroll
        for (int d = 16; d; d >>= 1) {
            conv += __shfl_xor_sync(0xffffffffu, conv, d);
            wsq  += __shfl_xor_sync(0xffffffffu, wsq,  d);
            xsq  += __shfl_xor_sync(0xffffffffu, xsq,  d);
        }
        if (lane == 0) {
            out[u] = -2.0f * (conv - 0.5f * xsq - 0.5f * wsq);
            g_max2[u] = 0ull;              // reset for next graph replay
        }
    }
}

extern "C" void kernel_launch(void* const* d_in, const int* in_sizes, int n_in,
                              void* d_out, int out_size) {
    const float* x = (const float*)d_in[0];
    const float* w = (const float*)d_in[1];
    float* out = (float*)d_out;

    cudaFuncSetAttribute(shapeconv_sel,
                         cudaFuncAttributeMaxDynamicSharedMemorySize, SMEM_BYTES);
    shapeconv_sel<<<NBLK, 256, SMEM_BYTES>>>(x, w);
    shapeconv_exact<<<128, 256>>>(x, w, out);
}

// round 14
// speedup vs baseline: 2.4636x; 2.4636x over previous
#include <cuda_runtime.h>
#include <cuda_fp16.h>
#include <cstdint>

// ShapeConv: fp16 mma.sync m16n8k16 with f16 ACCUMULATORS (2 output regs; on
// several archs this HMMA variant runs 2x the f32-accum rate) used for argmax
// selection only; exact fp32 recompute at the selected t restores accuracy.
// Selection+recompute machinery validated in R13 (passed, rel 3.9e-4, with
// far noisier int8 scores).

#define BB 32
#define CC 3
#define LL 8192
#define OO 128
#define KW 64
#define WW (LL - KW + 1)   /* 8129 valid windows */
#define KRED 192
#define APW 100            /* A pitch in 32-bit words (96 data + 4 pad) */
#define NBLK 296
#define NWRP (NBLK * 8)
#define WT_TOTAL (BB * 4 * 128)   /* 16384 warp-tiles: 32o x 64t */

#define A_OFF 0u           /* 128*APW f16x2 words = 51200 B */
#define P_OFF 51200u       /* 8 warps x 128 f32 prefix arrays */
#define SMEM_BYTES 55296

typedef unsigned long long ull;

__device__ ull g_max2[BB * OO];    // (mono(val)<<32 | t), zero-init, reset after read

__device__ __forceinline__ unsigned int f2mono(float f) {
    unsigned int u = __float_as_uint(f);
    return (u & 0x80000000u) ? ~u : (u | 0x80000000u);
}
__device__ __forceinline__ uint32_t pack_h2(float lo, float hi) {
    __half2 h = __floats2half2_rn(lo, hi);
    return *(uint32_t*)&h;
}
// f16-accumulator MMA: d/c are 2 regs (4 halves)
__device__ __forceinline__ void mma_f16a(uint32_t* d, const uint32_t* a,
                                         uint32_t b0, uint32_t b1) {
    asm volatile(
        "mma.sync.aligned.m16n8k16.row.col.f16.f16.f16.f16 "
        "{%0,%1}, {%2,%3,%4,%5}, {%6,%7}, {%0,%1};"
        : "+r"(d[0]), "+r"(d[1])
        : "r"(a[0]), "r"(a[1]), "r"(a[2]), "r"(a[3]), "r"(b0), "r"(b1));
}
__device__ __forceinline__ void ldsm_x4(uint32_t* a, uint32_t saddr) {
    asm volatile(
        "ldmatrix.sync.aligned.m8n8.x4.shared.b16 {%0,%1,%2,%3}, [%4];"
        : "=r"(a[0]), "=r"(a[1]), "=r"(a[2]), "=r"(a[3]) : "r"(saddr));
}

// ---------------- one warp-tile: 32 o x 64 t, K=192 ----------------
template <bool EDGE>
__device__ __forceinline__ void process_tile(
    const float* __restrict__ xb, int t0, uint32_t addrA0, uint32_t addrA1,
    float* __restrict__ Pw, int b, int os, int lane, int r4, int q4)
{
    __syncwarp();   // previous tile's Pw reads complete

    // ---- exclusive prefix of squared sums over [t0, t0+128) ----
    {
        int gi = t0 + 4 * lane;
        if (EDGE) gi = min(gi, LL - 4);
        float4 c0 = *(const float4*)(xb + gi);
        float4 c1 = *(const float4*)(xb + LL + gi);
        float4 c2 = *(const float4*)(xb + 2 * LL + gi);
        float s0 = c0.x*c0.x + c1.x*c1.x + c2.x*c2.x;
        float s1 = c0.y*c0.y + c1.y*c1.y + c2.y*c2.y;
        float s2 = c0.z*c0.z + c1.z*c1.z + c2.z*c2.z;
        float s3 = c0.w*c0.w + c1.w*c1.w + c2.w*c2.w;
        float e1 = s0, e2 = s0 + s1, e3 = e2 + s2, tot = e3 + s3;
        float sc = tot;
        #pragma unroll
        for (int d = 1; d < 32; d <<= 1) {
            float t = __shfl_up_sync(0xffffffffu, sc, d);
            if (lane >= d) sc += t;
        }
        float base = sc - tot;
        *(float4*)(Pw + 4*lane) = make_float4(base, base+e1, base+e2, base+e3);
    }
    __syncwarp();

    // ---- fp16 MMA mainloop (f16 accum), B frags straight from global ----
    uint32_t acc[2][8][2];
    #pragma unroll
    for (int mi = 0; mi < 2; ++mi)
        #pragma unroll
        for (int nf = 0; nf < 8; ++nf) { acc[mi][nf][0] = 0u; acc[mi][nf][1] = 0u; }

    const int off = t0 + r4 + 2 * q4;
    #pragma unroll
    for (int c = 0; c < CC; ++c) {
        const float* xc = xb + c * LL;
        uint32_t bb[15];
        #pragma unroll
        for (int u = 0; u < 15; ++u) {
            float v0, v1;
            if (EDGE) {
                int p = off + 8 * u;
                v0 = xc[min(p, LL - 1)];
                v1 = xc[min(p + 1, LL - 1)];
            } else {
                v0 = xc[off + 8 * u];
                v1 = xc[off + 8 * u + 1];
            }
            bb[u] = pack_h2(v0, v1);
        }
        #pragma unroll
        for (int j = 0; j < 4; ++j) {
            const uint32_t cb = (uint32_t)(c * 32 + j * 8) << 2;
            uint32_t a[2][4];
            ldsm_x4(a[0], addrA0 + cb);
            ldsm_x4(a[1], addrA1 + cb);
            #pragma unroll
            for (int nf = 0; nf < 8; ++nf) {
                uint32_t b0 = bb[2 * j + nf], b1 = bb[2 * j + nf + 1];
                mma_f16a(acc[0][nf], a[0], b0, b1);
                mma_f16a(acc[1][nf], a[1], b0, b1);
            }
        }
    }

    // ---- epilogue: (val, t) argmax per row with exact-win subtraction ----
    float mv[2][2];  int mx[2][2];
    #pragma unroll
    for (int mi = 0; mi < 2; ++mi)
        #pragma unroll
        for (int h = 0; h < 2; ++h) { mv[mi][h] = __int_as_float(0xff800000); mx[mi][h] = t0; }

    #pragma unroll
    for (int nf = 0; nf < 8; ++nf) {
        const int n0 = nf * 8 + 2 * q4;
        float w0 = 0.5f * (Pw[n0 + 64] - Pw[n0]);
        float w1 = 0.5f * (Pw[n0 + 65] - Pw[n0 + 1]);
        if (EDGE) {
            if (t0 + n0 >= WW)     w0 = __int_as_float(0x7f800000);
            if (t0 + n0 + 1 >= WW) w1 = __int_as_float(0x7f800000);
        }
        const int ti0 = t0 + n0, ti1 = t0 + n0 + 1;
        #pragma unroll
        for (int mi = 0; mi < 2; ++mi) {
            float2 lo = __half22float2(*(__half2*)&acc[mi][nf][0]);
            float2 hi = __half22float2(*(__half2*)&acc[mi][nf][1]);
            float f0 = lo.x - w0, f1 = lo.y - w1;
            float f2 = hi.x - w0, f3 = hi.y - w1;
            if (f0 > mv[mi][0]) { mv[mi][0] = f0; mx[mi][0] = ti0; }
            if (f1 > mv[mi][0]) { mv[mi][0] = f1; mx[mi][0] = ti1; }
            if (f2 > mv[mi][1]) { mv[mi][1] = f2; mx[mi][1] = ti0; }
            if (f3 > mv[mi][1]) { mv[mi][1] = f3; mx[mi][1] = ti1; }
        }
    }
    #pragma unroll
    for (int mi = 0; mi < 2; ++mi)
        #pragma unroll
        for (int h = 0; h < 2; ++h) {
            #pragma unroll
            for (int d = 1; d <= 2; d <<= 1) {
                float ov = __shfl_xor_sync(0xffffffffu, mv[mi][h], d);
                int   oi = __shfl_xor_sync(0xffffffffu, mx[mi][h], d);
                if (ov > mv[mi][h]) { mv[mi][h] = ov; mx[mi][h] = oi; }
            }
        }
    if (q4 == 0) {
        #pragma unroll
        for (int mi = 0; mi < 2; ++mi)
            #pragma unroll
            for (int h = 0; h < 2; ++h) {
                int row = os * 32 + mi * 16 + h * 8 + r4;
                ull pk = ((ull)f2mono(mv[mi][h]) << 32) | (unsigned)mx[mi][h];
                atomicMax(&g_max2[b * OO + row], pk);
            }
    }
}

extern "C" __global__ void __launch_bounds__(256, 2)
shapeconv_sel(const float* __restrict__ xg, const float* __restrict__ wg) {
    extern __shared__ char smem[];
    uint32_t* A_s = (uint32_t*)(smem + A_OFF);   // [128][APW] f16x2

    const int tid  = threadIdx.x;
    const int wid  = tid >> 5;
    const int lane = tid & 31;
    const int r4   = lane >> 2;
    const int q4   = lane & 3;

    float* Pw = (float*)(smem + P_OFF) + wid * 128;

    // ---- A staging: warp w owns o-rows [16w,16w+16); coalesced float2 -> f16x2
    {
        const int o0w = wid * 16;
        #pragma unroll 4
        for (int oi = 0; oi < 16; ++oi) {
            const int o = o0w + oi;
            const float2* wp = (const float2*)(wg + o * KRED);
            float2 v0 = wp[lane], v1 = wp[lane + 32], v2 = wp[lane + 64];
            uint32_t* ap = A_s + o * APW;
            ap[lane]      = pack_h2(v0.x, v0.y);
            ap[lane + 32] = pack_h2(v1.x, v1.y);
            ap[lane + 64] = pack_h2(v2.x, v2.y);
        }
    }
    __syncthreads();

    const uint32_t Abase = (uint32_t)__cvta_generic_to_shared(A_s);
    const uint32_t laneA = (uint32_t)(((lane & 15) * APW + ((lane >> 4) << 2)) << 2);

    // ---- warp-autonomous tiles: os fastest (x window reuse across o-slices)
    const int gw = blockIdx.x * 8 + wid;
    for (int widx = gw; widx < WT_TOTAL; widx += NWRP) {
        const int os = widx & 3;
        const int tw = (widx >> 2) & 127;
        const int b  = widx >> 9;
        const int t0 = tw << 6;
        const float* xb = xg + b * CC * LL;
        const uint32_t a0 = Abase + ((uint32_t)(os * 32 * APW) << 2) + laneA;
        const uint32_t a1 = a0 + ((16 * APW) << 2);
        if (tw == 127)
            process_tile<true >(xb, t0, a0, a1, Pw, b, os, lane, r4, q4);
        else
            process_tile<false>(xb, t0, a0, a1, Pw, b, os, lane, r4, q4);
    }
}

// ---- exact fp32 recompute of the selected feature per (b,o) + reset ----
extern "C" __global__ void __launch_bounds__(256)
shapeconv_exact(const float* __restrict__ xg, const float* __restrict__ wg,
                float* __restrict__ out) {
    const int wid  = threadIdx.x >> 5;
    const int lane = threadIdx.x & 31;
    const int gw   = blockIdx.x * 8 + wid;
    for (int u = gw; u < BB * OO; u += 256 * 8) {
        ull pk = g_max2[u];
        int t = (int)(unsigned)(pk & 0xffffffffu);
        int b = u >> 7, o = u & (OO - 1);
        float conv = 0.f, wsq = 0.f, xsq = 0.f;
        #pragma unroll
        for (int j = 0; j < 6; ++j) {
            int kl = lane + 32 * j;
            int c = kl >> 6, k = kl & 63;
            float wv = wg[o * KRED + kl];
            float xv = xg[(b * CC + c) * LL + t + k];
            conv = fmaf(wv, xv, conv);
            wsq  = fmaf(wv, wv, wsq);
            xsq  = fmaf(xv, xv, xsq);
        }
        #pragma unroll
        for (int d = 16; d; d >>= 1) {
            conv += __shfl_xor_sync(0xffffffffu, conv, d);
            wsq  += __shfl_xor_sync(0xffffffffu, wsq,  d);
            xsq  += __shfl_xor_sync(0xffffffffu, xsq,  d);
        }
        if (lane == 0) {
            out[u] = -2.0f * (conv - 0.5f * xsq - 0.5f * wsq);
            g_max2[u] = 0ull;              // reset for next graph replay
        }
    }
}

extern "C" void kernel_launch(void* const* d_in, const int* in_sizes, int n_in,
                              void* d_out, int out_size) {
    const float* x = (const float*)d_in[0];
    const float* w = (const float*)d_in[1];
    float* out = (float*)d_out;

    cudaFuncSetAttribute(shapeconv_sel,
                         cudaFuncAttributeMaxDynamicSharedMemorySize, SMEM_BYTES);
    shapeconv_sel<<<NBLK, 256, SMEM_BYTES>>>(x, w);
    shapeconv_exact<<<256, 256>>>(x, w, out);
}